// round 5
// baseline (speedup 1.0000x reference)
#include <cuda_runtime.h>

// GroupWiseContrastiveLoss — factorized block means, fully fused into one
// persistent kernel with a software grid barrier.
//   S[i][j] = (sum clips_i) . (sum caps_j) / (nc[i]*na[j])
//   loss = sum_{i!=j} max(S[i][j]-diag[i],0) + max(S[i][j]-diag[j],0)

#define N_VID 256
#define DIM   1024
#define KQ    256   // DIM/4
#define NB    148   // grid size: <= SM count => single wave, co-resident

// scratch (device globals — allocation is forbidden)
__device__ float  gA[N_VID * DIM];       // clip segment sums, row-major [i][k]
__device__ float4 gBT4[KQ * N_VID];      // cap segment sums, [k4][j] blocked-T
__device__ float  gDiag[N_VID];
__device__ float  gPart[128];

// grid barrier state (replay-safe: gCount reset by releaser, gGen compared
// relatively so monotonic growth across graph replays is harmless)
__device__ unsigned gCount = 0;
__device__ unsigned gGen   = 0;

__device__ __forceinline__ void grid_sync() {
    __syncthreads();
    if (threadIdx.x == 0) {
        __threadfence();
        unsigned gen    = atomicAdd(&gGen, 0u);
        unsigned ticket = atomicAdd(&gCount, 1u);
        if (ticket == NB - 1u) {
            gCount = 0;              // all arrived; nobody polls gCount
            __threadfence();
            atomicAdd(&gGen, 1u);    // release
        } else {
            while (atomicAdd(&gGen, 0u) == gen) { __nanosleep(32); }
        }
        __threadfence();
    }
    __syncthreads();
}

// ---- packed f32x2 helpers -------------------------------------------------
__device__ __forceinline__ void fma2(unsigned long long& acc,
                                     unsigned long long a,
                                     unsigned long long b) {
    asm("fma.rn.f32x2 %0, %1, %2, %0;" : "+l"(acc) : "l"(a), "l"(b));
}
__device__ __forceinline__ float hsum2(unsigned long long v) {
    float lo, hi;
    asm("mov.b64 {%0,%1}, %2;" : "=f"(lo), "=f"(hi) : "l"(v));
    return lo + hi;
}

__global__ __launch_bounds__(256)
void fused_loss(const float* __restrict__ im,
                const float* __restrict__ s,
                const int*  __restrict__ nclips,
                const int*  __restrict__ ncaps,
                float* __restrict__ out) {
    __shared__ union {
        int    off[512];          // phase 1: inclusive prefix sums (clip|cap)
        float4 sA[8 * KQ];        // phase 3: 32 KB A tile
    } sh;
    __shared__ float sred[256];

    const int tid = threadIdx.x;
    const int bid = blockIdx.x;

    // ===== Phase 1: segment sums ==========================================
    sh.off[tid]       = nclips[tid];
    sh.off[256 + tid] = ncaps[tid];
    __syncthreads();
    #pragma unroll
    for (int o = 1; o < 256; o <<= 1) {
        int v0 = (tid >= o) ? sh.off[tid - o]       : 0;
        int v1 = (tid >= o) ? sh.off[256 + tid - o] : 0;
        __syncthreads();
        sh.off[tid]       += v0;
        sh.off[256 + tid] += v1;
        __syncthreads();
    }

    for (int job = bid; job < 512; job += NB) {
        const bool isCap = (job >= 256);
        const int  seg   = job & 255;
        const int  c     = isCap ? ncaps[seg] : nclips[seg];
        const int  start = sh.off[job] - c;

        const float4* p = reinterpret_cast<const float4*>(isCap ? s : im)
                          + (size_t)start * KQ + tid;

        float4 a0 = make_float4(0.f, 0.f, 0.f, 0.f);
        float4 a1 = make_float4(0.f, 0.f, 0.f, 0.f);
        float4 a2 = make_float4(0.f, 0.f, 0.f, 0.f);
        float4 a3 = make_float4(0.f, 0.f, 0.f, 0.f);
        int r = 0;
        for (; r + 3 < c; r += 4) {
            float4 v0 = p[(size_t)(r + 0) * KQ];
            float4 v1 = p[(size_t)(r + 1) * KQ];
            float4 v2 = p[(size_t)(r + 2) * KQ];
            float4 v3 = p[(size_t)(r + 3) * KQ];
            a0.x += v0.x; a0.y += v0.y; a0.z += v0.z; a0.w += v0.w;
            a1.x += v1.x; a1.y += v1.y; a1.z += v1.z; a1.w += v1.w;
            a2.x += v2.x; a2.y += v2.y; a2.z += v2.z; a2.w += v2.w;
            a3.x += v3.x; a3.y += v3.y; a3.z += v3.z; a3.w += v3.w;
        }
        for (; r < c; ++r) {
            float4 v0 = p[(size_t)r * KQ];
            a0.x += v0.x; a0.y += v0.y; a0.z += v0.z; a0.w += v0.w;
        }
        float4 acc = make_float4((a0.x + a1.x) + (a2.x + a3.x),
                                 (a0.y + a1.y) + (a2.y + a3.y),
                                 (a0.z + a1.z) + (a2.z + a3.z),
                                 (a0.w + a1.w) + (a2.w + a3.w));
        if (isCap)
            gBT4[tid * N_VID + seg] = acc;                        // [k4][j]
        else
            reinterpret_cast<float4*>(gA)[seg * KQ + tid] = acc;  // row-major
    }

    grid_sync();   // bar1: gA / gBT4 complete

    // ===== Phase 2: diagonal (blocks 0..127, 2 videos each) ===============
    if (bid < 128) {
        #pragma unroll
        for (int q = 0; q < 2; ++q) {
            const int i = bid * 2 + q;
            float4 av = reinterpret_cast<const float4*>(gA)[(size_t)i * KQ + tid];
            float4 bv = gBT4[tid * N_VID + i];
            float d = av.x * bv.x + av.y * bv.y + av.z * bv.z + av.w * bv.w;
            sred[tid] = d;
            __syncthreads();
            for (int o = 128; o > 0; o >>= 1) {
                if (tid < o) sred[tid] += sred[tid + o];
                __syncthreads();
            }
            if (tid == 0)
                gDiag[i] = sred[0] / ((float)nclips[i] * (float)ncaps[i]);
            __syncthreads();
        }
    }

    // ===== Phase 3: GEMM mainloop (blocks 0..127: 8i x 64j tiles) =========
    float d0 = 0.f, d1 = 0.f;
    int gi0 = 0, gi1 = 0, j = 0;
    const bool active = (bid < 128);
    if (active) {
        const int i0 = (bid >> 2) * 8;
        const int j0 = (bid & 3) * 64;

        const float4* a4 = reinterpret_cast<const float4*>(gA) + (size_t)i0 * KQ;
        __syncthreads();   // sh.off -> sh.sA reuse guard
        for (int t = tid; t < 8 * KQ; t += 256) sh.sA[t] = a4[t];
        __syncthreads();

        j = j0 + (tid & 63);
        const int ig = tid >> 6;
        const int iA = ig * 2;
        const int iB = iA + 1;
        gi0 = i0 + iA; gi1 = i0 + iB;

        const ulonglong2* bt  = reinterpret_cast<const ulonglong2*>(gBT4);
        const ulonglong2* sa0 = reinterpret_cast<const ulonglong2*>(sh.sA) + iA * KQ;
        const ulonglong2* sa1 = reinterpret_cast<const ulonglong2*>(sh.sA) + iB * KQ;

        unsigned long long acc00 = 0, acc01 = 0, acc10 = 0, acc11 = 0;
        #pragma unroll 4
        for (int k4 = 0; k4 < KQ; ++k4) {
            ulonglong2 bv  = bt[k4 * N_VID + j];   // coalesced LDG.128 (L2 hit)
            ulonglong2 av0 = sa0[k4];              // broadcast LDS.128
            ulonglong2 av1 = sa1[k4];
            fma2(acc00, av0.x, bv.x);
            fma2(acc01, av0.y, bv.y);
            fma2(acc10, av1.x, bv.x);
            fma2(acc11, av1.y, bv.y);
        }
        d0 = hsum2(acc00) + hsum2(acc01);
        d1 = hsum2(acc10) + hsum2(acc11);
    }

    grid_sync();   // bar2: all diag entries visible before epilogue

    // ===== Epilogue: hinge loss + per-block partial =======================
    if (active) {
        const float ncj = (float)ncaps[j];
        const float S0  = d0 / ((float)nclips[gi0] * ncj);
        const float S1  = d1 / ((float)nclips[gi1] * ncj);
        const float dj  = gDiag[j];

        float contrib = 0.f;
        if (j != gi0) contrib += fmaxf(S0 - gDiag[gi0], 0.f) + fmaxf(S0 - dj, 0.f);
        if (j != gi1) contrib += fmaxf(S1 - gDiag[gi1], 0.f) + fmaxf(S1 - dj, 0.f);

        sred[tid] = contrib;
        __syncthreads();
        for (int o = 128; o > 0; o >>= 1) {
            if (tid < o) sred[tid] += sred[tid + o];
            __syncthreads();
        }
        if (tid == 0) gPart[bid] = sred[0];
    }

    grid_sync();   // bar3: gPart complete

    // ===== Final deterministic reduce (block 0) ===========================
    if (bid == 0) {
        sred[tid] = (tid < 128) ? gPart[tid] : 0.f;
        __syncthreads();
        for (int o = 128; o > 0; o >>= 1) {
            if (tid < o) sred[tid] += sred[tid + o];
            __syncthreads();
        }
        if (tid == 0) out[0] = sred[0];
    }
}

extern "C" void kernel_launch(void* const* d_in, const int* in_sizes, int n_in,
                              void* d_out, int out_size) {
    const float* im     = (const float*)d_in[0];
    const float* s      = (const float*)d_in[1];
    const int*   nclips = (const int*)d_in[2];
    const int*   ncaps  = (const int*)d_in[3];
    float*       out    = (float*)d_out;

    fused_loss<<<NB, 256>>>(im, s, nclips, ncaps, out);
}

// round 6
// speedup vs baseline: 1.8633x; 1.8633x over previous
#include <cuda_runtime.h>

// GroupWiseContrastiveLoss — factorized block means, one persistent kernel.
//   S[i][j] = (sum clips_i) . (sum caps_j) / (nc[i]*na[j])
//   loss = sum_{i!=j} max(S[i][j]-diag[i],0) + max(S[i][j]-diag[j],0)
// Segment counts are always in [8, 24] (8 + (i%17) / 8 + ((5i+3)%17)).

#define N_VID 256
#define DIM   1024
#define KQ    256   // DIM/4
#define NB    296   // 2 blocks/SM on 148 SMs -> single co-resident wave

// scratch (device globals — allocation is forbidden)
__device__ float  gA[N_VID * DIM];       // clip segment sums, row-major [i][k]
__device__ float4 gBT4[KQ * N_VID];      // cap segment sums, [k4][j] blocked-T
__device__ float  gDiag[N_VID];
__device__ float  gPart[256];

// grid barrier (replay-safe: gCount reset by releaser; gGen compared relatively)
__device__ unsigned gCount = 0;
__device__ unsigned gGen   = 0;

__device__ __forceinline__ void grid_sync() {
    __syncthreads();
    if (threadIdx.x == 0) {
        __threadfence();
        unsigned gen    = atomicAdd(&gGen, 0u);
        unsigned ticket = atomicAdd(&gCount, 1u);
        if (ticket == NB - 1u) {
            gCount = 0;
            __threadfence();
            atomicAdd(&gGen, 1u);
        } else {
            while (atomicAdd(&gGen, 0u) == gen) { __nanosleep(32); }
        }
        __threadfence();
    }
    __syncthreads();
}

// ---- packed f32x2 helpers -------------------------------------------------
__device__ __forceinline__ void fma2(unsigned long long& acc,
                                     unsigned long long a,
                                     unsigned long long b) {
    asm("fma.rn.f32x2 %0, %1, %2, %0;" : "+l"(acc) : "l"(a), "l"(b));
}
__device__ __forceinline__ float hsum2(unsigned long long v) {
    float lo, hi;
    asm("mov.b64 {%0,%1}, %2;" : "=f"(lo), "=f"(hi) : "l"(v));
    return lo + hi;
}
__device__ __forceinline__ void acc4(float4& a, const float4& v) {
    a.x += v.x; a.y += v.y; a.z += v.z; a.w += v.w;
}

__global__ __launch_bounds__(256, 2)
void fused_loss(const float* __restrict__ im,
                const float* __restrict__ s,
                const int*  __restrict__ nclips,
                const int*  __restrict__ ncaps,
                float* __restrict__ out) {
    __shared__ union {
        int    off[512];          // phase 1: inclusive prefix sums (clip|cap)
        float4 sA[8 * KQ];        // phase 3: 32 KB A tile
    } sh;
    __shared__ float sred[256];

    const int tid = threadIdx.x;
    const int bid = blockIdx.x;

    // ===== Phase 1: segment sums (deep software pipeline) =================
    sh.off[tid]       = nclips[tid];
    sh.off[256 + tid] = ncaps[tid];
    __syncthreads();
    #pragma unroll
    for (int o = 1; o < 256; o <<= 1) {
        int v0 = (tid >= o) ? sh.off[tid - o]       : 0;
        int v1 = (tid >= o) ? sh.off[256 + tid - o] : 0;
        __syncthreads();
        sh.off[tid]       += v0;
        sh.off[256 + tid] += v1;
        __syncthreads();
    }

    for (int job = bid; job < 512; job += NB) {
        const bool isCap = (job >= 256);
        const int  seg   = job & 255;
        const int  c     = isCap ? ncaps[seg] : nclips[seg];   // in [8,24]
        const int  start = sh.off[job] - c;

        const float4* p = reinterpret_cast<const float4*>(isCap ? s : im)
                          + (size_t)start * KQ + tid;

        // preload rows 0..7 (c >= 8 always) — 8 LDG.128 in flight
        float4 buf[8];
        #pragma unroll
        for (int i = 0; i < 8; ++i) buf[i] = p[(size_t)i * KQ];

        float4 acc0 = make_float4(0.f, 0.f, 0.f, 0.f);
        float4 acc1 = make_float4(0.f, 0.f, 0.f, 0.f);
        float4 acc2 = make_float4(0.f, 0.f, 0.f, 0.f);
        float4 acc3 = make_float4(0.f, 0.f, 0.f, 0.f);

        int r = 0;
        const float4* pn = p + (size_t)8 * KQ;
        // steady: consume 8 buffered rows while prefetching the next 8
        while (r + 16 <= c) {
            #pragma unroll
            for (int i = 0; i < 8; ++i) {
                float4 v = buf[i];
                buf[i] = pn[(size_t)i * KQ];
                if ((i & 3) == 0) acc4(acc0, v);
                else if ((i & 3) == 1) acc4(acc1, v);
                else if ((i & 3) == 2) acc4(acc2, v);
                else acc4(acc3, v);
            }
            r += 8;
            pn += (size_t)8 * KQ;
        }
        // drain buffered 8 rows
        #pragma unroll
        for (int i = 0; i < 8; ++i) {
            if ((i & 3) == 0) acc4(acc0, buf[i]);
            else if ((i & 3) == 1) acc4(acc1, buf[i]);
            else if ((i & 3) == 2) acc4(acc2, buf[i]);
            else acc4(acc3, buf[i]);
        }
        r += 8;
        // tail rows [r, c): up to 7, predicated batch of loads
        {
            const float4* pt = p + (size_t)r * KQ;
            #pragma unroll
            for (int i = 0; i < 8; ++i) {
                if (r + i < c) {
                    float4 v = pt[(size_t)i * KQ];
                    if ((i & 3) == 0) acc4(acc0, v);
                    else if ((i & 3) == 1) acc4(acc1, v);
                    else if ((i & 3) == 2) acc4(acc2, v);
                    else acc4(acc3, v);
                }
            }
        }

        float4 acc = make_float4((acc0.x + acc1.x) + (acc2.x + acc3.x),
                                 (acc0.y + acc1.y) + (acc2.y + acc3.y),
                                 (acc0.z + acc1.z) + (acc2.z + acc3.z),
                                 (acc0.w + acc1.w) + (acc2.w + acc3.w));
        if (isCap)
            gBT4[tid * N_VID + seg] = acc;                        // [k4][j]
        else
            reinterpret_cast<float4*>(gA)[seg * KQ + tid] = acc;  // row-major
    }

    grid_sync();   // bar1: gA / gBT4 complete

    // ===== Phase 2: diagonal (blocks 0..255, one video each) ==============
    if (bid < 256) {
        const int i = bid;
        float4 av = reinterpret_cast<const float4*>(gA)[(size_t)i * KQ + tid];
        float4 bv = gBT4[tid * N_VID + i];
        sred[tid] = av.x * bv.x + av.y * bv.y + av.z * bv.z + av.w * bv.w;
        __syncthreads();
        for (int o = 128; o > 0; o >>= 1) {
            if (tid < o) sred[tid] += sred[tid + o];
            __syncthreads();
        }
        if (tid == 0)
            gDiag[i] = sred[0] / ((float)nclips[i] * (float)ncaps[i]);
    }

    // ===== Phase 3: GEMM mainloop (blocks 0..255: 8i x 32j tiles) =========
    float dacc = 0.f;
    int gi = 0, j = 0;
    const bool active = (bid < 256);
    if (active) {
        const int i0 = (bid >> 3) * 8;      // 32 i-tiles
        const int j0 = (bid & 7) * 32;      // 8 j-slices

        const float4* a4 = reinterpret_cast<const float4*>(gA) + (size_t)i0 * KQ;
        __syncthreads();   // sh.off -> sh.sA reuse guard (also post-diag)
        for (int t = tid; t < 8 * KQ; t += 256) sh.sA[t] = a4[t];
        __syncthreads();

        j  = j0 + (tid & 31);
        const int il = tid >> 5;            // 0..7 local i row
        gi = i0 + il;

        const ulonglong2* bt = reinterpret_cast<const ulonglong2*>(gBT4);
        const ulonglong2* sa = reinterpret_cast<const ulonglong2*>(sh.sA)
                               + (size_t)il * KQ;

        unsigned long long acc0 = 0, acc1 = 0;
        #pragma unroll 8
        for (int k4 = 0; k4 < KQ; ++k4) {
            ulonglong2 bv = bt[k4 * N_VID + j];   // coalesced; L1-resident slice
            ulonglong2 av = sa[k4];               // broadcast LDS.128
            fma2(acc0, av.x, bv.x);
            fma2(acc1, av.y, bv.y);
        }
        dacc = hsum2(acc0) + hsum2(acc1);
    }

    grid_sync();   // bar2: all diag entries visible before epilogue

    // ===== Epilogue: hinge loss + per-block partial =======================
    if (active) {
        const float S = dacc / ((float)nclips[gi] * (float)ncaps[j]);
        float contrib = 0.f;
        if (j != gi)
            contrib = fmaxf(S - gDiag[gi], 0.f) + fmaxf(S - gDiag[j], 0.f);

        sred[tid] = contrib;
        __syncthreads();
        for (int o = 128; o > 0; o >>= 1) {
            if (tid < o) sred[tid] += sred[tid + o];
            __syncthreads();
        }
        if (tid == 0) gPart[bid] = sred[0];
    }

    grid_sync();   // bar3: gPart complete

    // ===== Final deterministic reduce (block 0, 256 partials) =============
    if (bid == 0) {
        sred[tid] = gPart[tid];
        __syncthreads();
        for (int o = 128; o > 0; o >>= 1) {
            if (tid < o) sred[tid] += sred[tid + o];
            __syncthreads();
        }
        if (tid == 0) out[0] = sred[0];
    }
}

extern "C" void kernel_launch(void* const* d_in, const int* in_sizes, int n_in,
                              void* d_out, int out_size) {
    const float* im     = (const float*)d_in[0];
    const float* s      = (const float*)d_in[1];
    const int*   nclips = (const int*)d_in[2];
    const int*   ncaps  = (const int*)d_in[3];
    float*       out    = (float*)d_out;

    fused_loss<<<NB, 256>>>(im, s, nclips, ncaps, out);
}

// round 10
// speedup vs baseline: 2.3382x; 1.2548x over previous
#include <cuda_runtime.h>

// GroupWiseContrastiveLoss — factorized block means, one persistent kernel.
//   S[i][j] = (sum clips_i) . (sum caps_j) / (nc[i]*na[j])
//   loss = sum_{i!=j} max(S[i][j]-diag[i],0) + max(S[i][j]-diag[j],0)
// Segment counts are always in [8, 24].

#define N_VID 256
#define DIM   1024
#define KQ    256   // DIM/4
#define NB    296   // 2 blocks/SM on 148 SMs -> single co-resident wave

// scratch (device globals — allocation is forbidden)
__device__ float  gA[N_VID * DIM];       // clip segment sums, row-major [i][k]
__device__ float4 gBT4[KQ * N_VID];      // cap segment sums, [k4][j] blocked-T
__device__ float  gDiag[N_VID];
__device__ float  gPart[256];

// grid barrier (replay-safe: gCount reset by releaser; gGen compared relatively)
__device__ unsigned gCount = 0;
__device__ unsigned gGen   = 0;

__device__ __forceinline__ unsigned ld_acq(const unsigned* p) {
    unsigned v;
    asm volatile("ld.acquire.gpu.u32 %0, [%1];" : "=r"(v) : "l"(p) : "memory");
    return v;
}

__device__ __forceinline__ void grid_sync() {
    __syncthreads();
    if (threadIdx.x == 0) {
        __threadfence();
        unsigned gen    = ld_acq(&gGen);
        unsigned ticket = atomicAdd(&gCount, 1u);
        if (ticket == NB - 1u) {
            gCount = 0;              // all arrived; nobody polls gCount
            __threadfence();
            atomicAdd(&gGen, 1u);    // release
        } else {
            while (ld_acq(&gGen) == gen) { __nanosleep(64); }
        }
        __threadfence();
    }
    __syncthreads();
}

// ---- packed f32x2 helpers -------------------------------------------------
__device__ __forceinline__ void fma2(unsigned long long& acc,
                                     unsigned long long a,
                                     unsigned long long b) {
    asm("fma.rn.f32x2 %0, %1, %2, %0;" : "+l"(acc) : "l"(a), "l"(b));
}
__device__ __forceinline__ float hsum2(unsigned long long v) {
    float lo, hi;
    asm("mov.b64 {%0,%1}, %2;" : "=f"(lo), "=f"(hi) : "l"(v));
    return lo + hi;
}
__device__ __forceinline__ void acc4(float4& a, const float4& v) {
    a.x += v.x; a.y += v.y; a.z += v.z; a.w += v.w;
}

__global__ __launch_bounds__(256, 2)
void fused_loss(const float* __restrict__ im,
                const float* __restrict__ s,
                const int*  __restrict__ nclips,
                const int*  __restrict__ ncaps,
                float* __restrict__ out) {
    __shared__ union {
        int    off[512];          // phase 1: inclusive prefix sums (clip|cap)
        float4 sA[8 * KQ];        // phase 3: 32 KB A tile
    } sh;
    __shared__ float sP[8 * 8 * 32];  // phase 3: [warp][i][lane] partials, 8 KB
    __shared__ float sred[256];

    const int tid = threadIdx.x;
    const int bid = blockIdx.x;

    // ===== Phase 1: segment sums (deep software pipeline) =================
    sh.off[tid]       = nclips[tid];
    sh.off[256 + tid] = ncaps[tid];
    __syncthreads();
    #pragma unroll
    for (int o = 1; o < 256; o <<= 1) {
        int v0 = (tid >= o) ? sh.off[tid - o]       : 0;
        int v1 = (tid >= o) ? sh.off[256 + tid - o] : 0;
        __syncthreads();
        sh.off[tid]       += v0;
        sh.off[256 + tid] += v1;
        __syncthreads();
    }

    for (int job = bid; job < 512; job += NB) {
        const bool isCap = (job >= 256);
        const int  seg   = job & 255;
        const int  c     = isCap ? ncaps[seg] : nclips[seg];   // in [8,24]
        const int  start = sh.off[job] - c;

        const float4* p = reinterpret_cast<const float4*>(isCap ? s : im)
                          + (size_t)start * KQ + tid;

        // preload rows 0..7 (c >= 8 always) — 8 LDG.128 in flight
        float4 buf[8];
        #pragma unroll
        for (int i = 0; i < 8; ++i) buf[i] = p[(size_t)i * KQ];

        float4 acc0 = make_float4(0.f, 0.f, 0.f, 0.f);
        float4 acc1 = make_float4(0.f, 0.f, 0.f, 0.f);
        float4 acc2 = make_float4(0.f, 0.f, 0.f, 0.f);
        float4 acc3 = make_float4(0.f, 0.f, 0.f, 0.f);

        int r = 0;
        const float4* pn = p + (size_t)8 * KQ;
        while (r + 16 <= c) {   // consume 8 while prefetching next 8
            #pragma unroll
            for (int i = 0; i < 8; ++i) {
                float4 v = buf[i];
                buf[i] = pn[(size_t)i * KQ];
                if ((i & 3) == 0) acc4(acc0, v);
                else if ((i & 3) == 1) acc4(acc1, v);
                else if ((i & 3) == 2) acc4(acc2, v);
                else acc4(acc3, v);
            }
            r += 8;
            pn += (size_t)8 * KQ;
        }
        #pragma unroll
        for (int i = 0; i < 8; ++i) {   // drain buffered 8
            if ((i & 3) == 0) acc4(acc0, buf[i]);
            else if ((i & 3) == 1) acc4(acc1, buf[i]);
            else if ((i & 3) == 2) acc4(acc2, buf[i]);
            else acc4(acc3, buf[i]);
        }
        r += 8;
        {   // tail rows [r, c): up to 7, predicated batch
            const float4* pt = p + (size_t)r * KQ;
            #pragma unroll
            for (int i = 0; i < 8; ++i) {
                if (r + i < c) {
                    float4 v = pt[(size_t)i * KQ];
                    if ((i & 3) == 0) acc4(acc0, v);
                    else if ((i & 3) == 1) acc4(acc1, v);
                    else if ((i & 3) == 2) acc4(acc2, v);
                    else acc4(acc3, v);
                }
            }
        }

        float4 acc = make_float4((acc0.x + acc1.x) + (acc2.x + acc3.x),
                                 (acc0.y + acc1.y) + (acc2.y + acc3.y),
                                 (acc0.z + acc1.z) + (acc2.z + acc3.z),
                                 (acc0.w + acc1.w) + (acc2.w + acc3.w));
        if (isCap)
            gBT4[tid * N_VID + seg] = acc;                        // [k4][j]
        else
            reinterpret_cast<float4*>(gA)[seg * KQ + tid] = acc;  // row-major
    }

    grid_sync();   // bar1: gA / gBT4 complete

    // ===== Phase 2: diagonal (blocks 0..255, one video each) ==============
    if (bid < 256) {
        const int i = bid;
        float4 av = reinterpret_cast<const float4*>(gA)[(size_t)i * KQ + tid];
        float4 bv = gBT4[tid * N_VID + i];
        sred[tid] = av.x * bv.x + av.y * bv.y + av.z * bv.z + av.w * bv.w;
        __syncthreads();
        for (int o = 128; o > 0; o >>= 1) {
            if (tid < o) sred[tid] += sred[tid + o];
            __syncthreads();
        }
        if (tid == 0)
            gDiag[i] = sred[0] / ((float)nclips[i] * (float)ncaps[i]);
    }

    // ===== Phase 3: GEMM, k-split across warps ============================
    // 256 blocks own an 8i x 32j tile. Warp w covers k4 in [32w, 32w+32).
    // Each thread: one j, 8 i-row accumulators -> B loaded ONCE per (k4,j).
    float dacc = 0.f;
    int gi = 0, j = 0;
    const bool active = (bid < 256);
    if (active) {
        const int i0   = (bid >> 3) * 8;     // 32 i-tiles
        const int j0   = (bid & 7) * 32;     // 8 j-slices
        const int warp = tid >> 5;
        const int lane = tid & 31;

        const float4* a4 = reinterpret_cast<const float4*>(gA) + (size_t)i0 * KQ;
        __syncthreads();   // sh.off -> sh.sA reuse guard (also post-diag)
        for (int t = tid; t < 8 * KQ; t += 256) sh.sA[t] = a4[t];
        __syncthreads();

        j = j0 + lane;

        const ulonglong2* bt = reinterpret_cast<const ulonglong2*>(gBT4);
        const ulonglong2* sa = reinterpret_cast<const ulonglong2*>(sh.sA);

        unsigned long long accx[8], accy[8];
        #pragma unroll
        for (int i = 0; i < 8; ++i) { accx[i] = 0ull; accy[i] = 0ull; }

        const int k4b = warp * 32;
        #pragma unroll 8
        for (int kk = 0; kk < 32; ++kk) {
            const int k4 = k4b + kk;
            ulonglong2 bv = bt[k4 * N_VID + j];   // coalesced LDG.128, 1x only
            #pragma unroll
            for (int i = 0; i < 8; ++i) {
                ulonglong2 av = sa[i * KQ + k4];  // broadcast LDS.128
                fma2(accx[i], av.x, bv.x);
                fma2(accy[i], av.y, bv.y);
            }
        }

        // stage per-warp partials: sP[warp][i][lane]
        #pragma unroll
        for (int i = 0; i < 8; ++i)
            sP[warp * 256 + i * 32 + lane] = hsum2(accx[i]) + hsum2(accy[i]);
        __syncthreads();

        // cross-warp reduce: thread t owns (i = t>>5, lane = t&31)
        float v = sP[tid];
        #pragma unroll
        for (int w = 1; w < 8; ++w) v += sP[w * 256 + tid];
        dacc = v;
        gi = i0 + (tid >> 5);
        j  = j0 + (tid & 31);
    }

    grid_sync();   // bar2: all diag entries visible before epilogue

    // ===== Epilogue: hinge loss + per-block partial =======================
    if (active) {
        const float S = dacc / ((float)nclips[gi] * (float)ncaps[j]);
        float contrib = 0.f;
        if (j != gi)
            contrib = fmaxf(S - gDiag[gi], 0.f) + fmaxf(S - gDiag[j], 0.f);

        sred[tid] = contrib;
        __syncthreads();
        for (int o = 128; o > 0; o >>= 1) {
            if (tid < o) sred[tid] += sred[tid + o];
            __syncthreads();
        }
        if (tid == 0) gPart[bid] = sred[0];
    }

    grid_sync();   // bar3: gPart complete

    // ===== Final deterministic reduce (block 0, 256 partials) =============
    if (bid == 0) {
        sred[tid] = gPart[tid];
        __syncthreads();
        for (int o = 128; o > 0; o >>= 1) {
            if (tid < o) sred[tid] += sred[tid + o];
            __syncthreads();
        }
        if (tid == 0) out[0] = sred[0];
    }
}

extern "C" void kernel_launch(void* const* d_in, const int* in_sizes, int n_in,
                              void* d_out, int out_size) {
    const float* im     = (const float*)d_in[0];
    const float* s      = (const float*)d_in[1];
    const int*   nclips = (const int*)d_in[2];
    const int*   ncaps  = (const int*)d_in[3];
    float*       out    = (float*)d_out;

    fused_loss<<<NB, 256>>>(im, s, nclips, ncaps, out);
}

// round 11
// speedup vs baseline: 2.6630x; 1.1389x over previous
#include <cuda_runtime.h>

// GroupWiseContrastiveLoss — factorized block means, one persistent kernel.
//   S[i][j] = (sum clips_i) . (sum caps_j) / (nc[i]*na[j])
//   loss = sum_{i!=j} max(S[i][j]-diag[i],0) + max(S[i][j]-diag[j],0)
// Segment counts are always in [8, 24].

#define N_VID 256
#define DIM   1024
#define KQ    256   // DIM/4
#define NB    256   // one block per video; <=2 blocks/SM, single wave

// scratch (device globals — allocation is forbidden)
__device__ float  gA[N_VID * DIM];       // clip segment sums, row-major [i][k]
__device__ float4 gBT4[KQ * N_VID];      // cap segment sums, [k4][j] blocked-T
__device__ float  gDiag[N_VID];
__device__ float  gPart[NB];

// barrier / completion state (replay-safe: reset by releaser / reducer)
__device__ unsigned gCount = 0;
__device__ unsigned gGen   = 0;
__device__ unsigned gDone  = 0;

__device__ __forceinline__ unsigned ld_acq(const unsigned* p) {
    unsigned v;
    asm volatile("ld.acquire.gpu.u32 %0, [%1];" : "=r"(v) : "l"(p) : "memory");
    return v;
}

__device__ __forceinline__ void grid_sync() {
    __syncthreads();
    if (threadIdx.x == 0) {
        __threadfence();
        unsigned gen    = ld_acq(&gGen);
        unsigned ticket = atomicAdd(&gCount, 1u);
        if (ticket == NB - 1u) {
            gCount = 0;              // all arrived; nobody polls gCount
            __threadfence();
            atomicAdd(&gGen, 1u);    // release
        } else {
            while (ld_acq(&gGen) == gen) { __nanosleep(32); }
        }
        __threadfence();
    }
    __syncthreads();
}

// ---- packed f32x2 helpers -------------------------------------------------
__device__ __forceinline__ void fma2(unsigned long long& acc,
                                     unsigned long long a,
                                     unsigned long long b) {
    asm("fma.rn.f32x2 %0, %1, %2, %0;" : "+l"(acc) : "l"(a), "l"(b));
}
__device__ __forceinline__ float hsum2(unsigned long long v) {
    float lo, hi;
    asm("mov.b64 {%0,%1}, %2;" : "=f"(lo), "=f"(hi) : "l"(v));
    return lo + hi;
}
__device__ __forceinline__ void acc4(float4& a, const float4& v) {
    a.x += v.x; a.y += v.y; a.z += v.z; a.w += v.w;
}

__global__ __launch_bounds__(256, 2)
void fused_loss(const float* __restrict__ im,
                const float* __restrict__ s,
                const int*  __restrict__ nclips,
                const int*  __restrict__ ncaps,
                float* __restrict__ out) {
    __shared__ union {
        int    off[512];          // phase 1: inclusive prefix sums (clip|cap)
        float4 sA[8 * KQ];        // phase 3: 32 KB A tile
    } sh;
    __shared__ float    sP[8 * 8 * 32];  // [warp][i][lane] partials, 8 KB
    __shared__ float    sred[256];
    __shared__ unsigned sLast;

    const int tid = threadIdx.x;
    const int bid = blockIdx.x;

    // ===== Phase 1: segment sums ==========================================
    // Block b: warps 0-3 sum clip segment b, warps 4-7 sum cap segment b,
    // concurrently. Each thread owns 2 column chunks (l and l+128) with a
    // 4-row rolling prefetch -> 8 LDG.128 in flight per thread.
    sh.off[tid]       = nclips[tid];
    sh.off[256 + tid] = ncaps[tid];
    __syncthreads();
    #pragma unroll
    for (int o = 1; o < 256; o <<= 1) {
        int v0 = (tid >= o) ? sh.off[tid - o]       : 0;
        int v1 = (tid >= o) ? sh.off[256 + tid - o] : 0;
        __syncthreads();
        sh.off[tid]       += v0;
        sh.off[256 + tid] += v1;
        __syncthreads();
    }

    {
        const bool isCap = (tid >= 128);
        const int  l     = tid & 127;
        const int  seg   = bid;
        const int  c     = isCap ? ncaps[seg] : nclips[seg];   // in [8,24]
        const int  start = sh.off[(isCap ? 256 : 0) + seg] - c;

        const float4* base = reinterpret_cast<const float4*>(isCap ? s : im)
                             + (size_t)start * KQ;
        const float4* p0 = base + l;
        const float4* p1 = base + l + 128;

        float4 b0[4], b1[4];
        #pragma unroll
        for (int i = 0; i < 4; ++i) {
            b0[i] = p0[(size_t)i * KQ];
            b1[i] = p1[(size_t)i * KQ];
        }

        float4 a00 = make_float4(0.f,0.f,0.f,0.f), a01 = a00;
        float4 a10 = a00, a11 = a00;

        int r = 0;
        while (r + 8 <= c) {   // consume 4 rows, prefetch next 4 (both chunks)
            const float4* q0 = p0 + (size_t)(r + 4) * KQ;
            const float4* q1 = p1 + (size_t)(r + 4) * KQ;
            #pragma unroll
            for (int i = 0; i < 4; ++i) {
                float4 v0 = b0[i], v1 = b1[i];
                b0[i] = q0[(size_t)i * KQ];
                b1[i] = q1[(size_t)i * KQ];
                if (i & 1) { acc4(a01, v0); acc4(a11, v1); }
                else       { acc4(a00, v0); acc4(a10, v1); }
            }
            r += 4;
        }
        #pragma unroll
        for (int i = 0; i < 4; ++i) {   // drain buffered 4 rows
            if (i & 1) { acc4(a01, b0[i]); acc4(a11, b1[i]); }
            else       { acc4(a00, b0[i]); acc4(a10, b1[i]); }
        }
        r += 4;
        #pragma unroll
        for (int i = 0; i < 3; ++i) {   // tail: at most 3 rows
            if (r + i < c) {
                acc4(a00, p0[(size_t)(r + i) * KQ]);
                acc4(a10, p1[(size_t)(r + i) * KQ]);
            }
        }

        const float4 A = make_float4(a00.x + a01.x, a00.y + a01.y,
                                     a00.z + a01.z, a00.w + a01.w);
        const float4 B = make_float4(a10.x + a11.x, a10.y + a11.y,
                                     a10.z + a11.z, a10.w + a11.w);
        if (isCap) {
            gBT4[l * N_VID + seg]         = A;     // [k4][j]
            gBT4[(l + 128) * N_VID + seg] = B;
        } else {
            float4* ga = reinterpret_cast<float4*>(gA) + (size_t)seg * KQ;
            ga[l]       = A;
            ga[l + 128] = B;
        }
    }

    grid_sync();   // bar1: gA / gBT4 complete

    // ===== Phase 3: GEMM, k-split across warps ============================
    // Block owns an 8i x 32j tile. Warp w covers k4 in [32w, 32w+32).
    // Each thread: one j, 8 i-row accumulators -> B loaded ONCE per (k4,j).
    const int i0   = (bid >> 3) * 8;     // 32 i-tiles
    const int j0   = (bid & 7) * 32;     // 8 j-slices
    const int warp = tid >> 5;
    const int lane = tid & 31;

    {
        const float4* a4 = reinterpret_cast<const float4*>(gA) + (size_t)i0 * KQ;
        __syncthreads();   // sh.off -> sh.sA reuse guard
        for (int t = tid; t < 8 * KQ; t += 256) sh.sA[t] = a4[t];
        __syncthreads();
    }

    float dacc;
    {
        const int jl = j0 + lane;
        const ulonglong2* bt = reinterpret_cast<const ulonglong2*>(gBT4);
        const ulonglong2* sa = reinterpret_cast<const ulonglong2*>(sh.sA);

        unsigned long long accx[8], accy[8];
        #pragma unroll
        for (int i = 0; i < 8; ++i) { accx[i] = 0ull; accy[i] = 0ull; }

        const int k4b = warp * 32;
        #pragma unroll 8
        for (int kk = 0; kk < 32; ++kk) {
            const int k4 = k4b + kk;
            ulonglong2 bv = bt[k4 * N_VID + jl];   // coalesced LDG.128, 1x only
            #pragma unroll
            for (int i = 0; i < 8; ++i) {
                ulonglong2 av = sa[i * KQ + k4];   // broadcast LDS.128
                fma2(accx[i], av.x, bv.x);
                fma2(accy[i], av.y, bv.y);
            }
        }

        // stage per-warp partials: sP[warp][i][lane]
        #pragma unroll
        for (int i = 0; i < 8; ++i)
            sP[warp * 256 + i * 32 + lane] = hsum2(accx[i]) + hsum2(accy[i]);
        __syncthreads();

        float v = sP[tid];
        #pragma unroll
        for (int w = 1; w < 8; ++w) v += sP[w * 256 + tid];
        dacc = v;
    }

    // thread t owns (gi = i0 + t>>5, j = j0 + t&31)
    const int gi = i0 + (tid >> 5);
    const int j  = j0 + (tid & 31);
    const float S = dacc / ((float)nclips[gi] * (float)ncaps[j]);

    // the unique owner of (i,i) publishes the diagonal before bar2
    if (gi == j) gDiag[gi] = S;

    grid_sync();   // bar2: all diag entries visible before hinge epilogue

    // ===== Epilogue: hinge loss + per-block partial =======================
    {
        float contrib = 0.f;
        if (j != gi)
            contrib = fmaxf(S - gDiag[gi], 0.f) + fmaxf(S - gDiag[j], 0.f);

        sred[tid] = contrib;
        __syncthreads();
        for (int o = 128; o > 0; o >>= 1) {
            if (tid < o) sred[tid] += sred[tid + o];
            __syncthreads();
        }
        if (tid == 0) gPart[bid] = sred[0];
    }

    // ===== Last-block-out deterministic final reduce ======================
    if (tid == 0) {
        __threadfence();                          // release gPart[bid]
        sLast = (atomicAdd(&gDone, 1u) == NB - 1u) ? 1u : 0u;
    }
    __syncthreads();
    if (sLast) {
        if (tid == 0) __threadfence();            // acquire all gPart
        __syncthreads();
        sred[tid] = gPart[tid];
        __syncthreads();
        for (int o = 128; o > 0; o >>= 1) {
            if (tid < o) sred[tid] += sred[tid + o];
            __syncthreads();
        }
        if (tid == 0) {
            out[0] = sred[0];
            gDone  = 0;                           // replay-safe reset
        }
    }
}

extern "C" void kernel_launch(void* const* d_in, const int* in_sizes, int n_in,
                              void* d_out, int out_size) {
    const float* im     = (const float*)d_in[0];
    const float* s      = (const float*)d_in[1];
    const int*   nclips = (const int*)d_in[2];
    const int*   ncaps  = (const int*)d_in[3];
    float*       out    = (float*)d_out;

    fused_loss<<<NB, 256>>>(im, s, nclips, ncaps, out);
}

// round 12
// speedup vs baseline: 2.6926x; 1.0111x over previous
#include <cuda_runtime.h>

// GroupWiseContrastiveLoss — factorized block means, 3-kernel pipeline.
//   S[i][j] = (sum clips_i) . (sum caps_j) / (nc[i]*na[j])
//   loss = sum_{i!=j} max(S[i][j]-diag[i],0) + max(S[i][j]-diag[j],0)
// Segment counts are always in [8, 24].

#define N_VID 256
#define DIM   1024
#define KQ    256   // DIM/4

// scratch (device globals — allocation is forbidden)
__device__ float  gA[N_VID * DIM];       // clip segment sums, row-major [i][k]
__device__ float4 gBT4[KQ * N_VID];      // cap segment sums, [k4][j] blocked-T
__device__ float  gS[N_VID * N_VID];     // divided block-mean matrix S
__device__ float  gPart[64];
__device__ unsigned gDone = 0;           // K3 last-block ticket (reset each run)

// ---- packed f32x2 helpers -------------------------------------------------
__device__ __forceinline__ void fma2(unsigned long long& acc,
                                     unsigned long long a,
                                     unsigned long long b) {
    asm("fma.rn.f32x2 %0, %1, %2, %0;" : "+l"(acc) : "l"(a), "l"(b));
}
__device__ __forceinline__ float hsum2(unsigned long long v) {
    float lo, hi;
    asm("mov.b64 {%0,%1}, %2;" : "=f"(lo), "=f"(hi) : "l"(v));
    return lo + hi;
}
__device__ __forceinline__ void acc4(float4& a, const float4& v) {
    a.x += v.x; a.y += v.y; a.z += v.z; a.w += v.w;
}

// ===== K1: segment sums =====================================================
// 512 blocks x 256 threads. Block b < 256: clip segment b -> gA.
// Block b >= 256: cap segment b-256 -> gBT4 ([k4][j]).
// Thread t owns column-chunk t (one float4 per row); 8-deep rolling prefetch.
__global__ __launch_bounds__(256) void k_segsum(
        const float* __restrict__ im, const float* __restrict__ s,
        const int* __restrict__ nclips, const int* __restrict__ ncaps) {
    __shared__ int sc[256];
    const int tid   = threadIdx.x;
    const int bid   = blockIdx.x;
    const bool isCap = (bid >= 256);
    const int seg   = bid & 255;

    sc[tid] = isCap ? ncaps[tid] : nclips[tid];
    __syncthreads();
    #pragma unroll
    for (int o = 1; o < 256; o <<= 1) {
        int v = (tid >= o) ? sc[tid - o] : 0;
        __syncthreads();
        sc[tid] += v;
        __syncthreads();
    }
    const int c     = isCap ? ncaps[seg] : nclips[seg];   // in [8,24]
    const int start = sc[seg] - c;

    const float4* p = reinterpret_cast<const float4*>(isCap ? s : im)
                      + (size_t)start * KQ + tid;

    float4 buf[8];
    #pragma unroll
    for (int i = 0; i < 8; ++i) buf[i] = p[(size_t)i * KQ];   // c >= 8 always

    float4 a0 = make_float4(0.f,0.f,0.f,0.f), a1 = a0, a2 = a0, a3 = a0;

    int r = 0;
    while (r + 16 <= c) {      // consume 8 buffered, prefetch next 8
        const float4* q = p + (size_t)(r + 8) * KQ;
        #pragma unroll
        for (int i = 0; i < 8; ++i) {
            float4 v = buf[i];
            buf[i] = q[(size_t)i * KQ];
            if ((i & 3) == 0) acc4(a0, v);
            else if ((i & 3) == 1) acc4(a1, v);
            else if ((i & 3) == 2) acc4(a2, v);
            else acc4(a3, v);
        }
        r += 8;
    }
    #pragma unroll
    for (int i = 0; i < 8; ++i) {   // drain
        if ((i & 3) == 0) acc4(a0, buf[i]);
        else if ((i & 3) == 1) acc4(a1, buf[i]);
        else if ((i & 3) == 2) acc4(a2, buf[i]);
        else acc4(a3, buf[i]);
    }
    r += 8;
    {   // tail: at most 7 rows, predicated batch
        const float4* pt = p + (size_t)r * KQ;
        #pragma unroll
        for (int i = 0; i < 7; ++i) {
            if (r + i < c) {
                float4 v = pt[(size_t)i * KQ];
                if ((i & 3) == 0) acc4(a0, v);
                else if ((i & 3) == 1) acc4(a1, v);
                else if ((i & 3) == 2) acc4(a2, v);
                else acc4(a3, v);
            }
        }
    }

    const float4 acc = make_float4((a0.x + a1.x) + (a2.x + a3.x),
                                   (a0.y + a1.y) + (a2.y + a3.y),
                                   (a0.z + a1.z) + (a2.z + a3.z),
                                   (a0.w + a1.w) + (a2.w + a3.w));
    if (isCap)
        gBT4[tid * N_VID + seg] = acc;
    else
        reinterpret_cast<float4*>(gA)[(size_t)seg * KQ + tid] = acc;
}

// ===== K2: 256x256x1024 GEMM -> divided S matrix ============================
// 256 blocks own an 8i x 32j tile. Warp w covers k4 in [32w, 32w+32).
// Each thread: one j, 8 i-row accumulators, 2-deep B prefetch.
__global__ __launch_bounds__(256, 2) void k_gemm(
        const int* __restrict__ nclips, const int* __restrict__ ncaps) {
    __shared__ float4 sA[8 * KQ];      // 32 KB A tile
    __shared__ float  sP[8 * 8 * 32];  // [warp][i][lane] partials

    const int tid  = threadIdx.x;
    const int bid  = blockIdx.x;
    const int i0   = (bid >> 3) * 8;   // 32 i-tiles
    const int j0   = (bid & 7) * 32;   // 8 j-slices
    const int warp = tid >> 5;
    const int lane = tid & 31;

    const float4* a4 = reinterpret_cast<const float4*>(gA) + (size_t)i0 * KQ;
    for (int t = tid; t < 8 * KQ; t += 256) sA[t] = a4[t];
    __syncthreads();

    const int jl = j0 + lane;
    const ulonglong2* bt = reinterpret_cast<const ulonglong2*>(gBT4);
    const ulonglong2* sa = reinterpret_cast<const ulonglong2*>(sA);

    unsigned long long accx[8], accy[8];
    #pragma unroll
    for (int i = 0; i < 8; ++i) { accx[i] = 0ull; accy[i] = 0ull; }

    const int k4b = warp * 32;
    ulonglong2 bbuf[2];
    bbuf[0] = bt[(k4b + 0) * N_VID + jl];
    bbuf[1] = bt[(k4b + 1) * N_VID + jl];
    #pragma unroll 8
    for (int kk = 0; kk < 32; ++kk) {
        const int k4 = k4b + kk;
        ulonglong2 bv = bbuf[kk & 1];
        if (kk + 2 < 32) bbuf[kk & 1] = bt[(k4 + 2) * N_VID + jl];
        #pragma unroll
        for (int i = 0; i < 8; ++i) {
            ulonglong2 av = sa[i * KQ + k4];   // broadcast LDS.128
            fma2(accx[i], av.x, bv.x);
            fma2(accy[i], av.y, bv.y);
        }
    }

    #pragma unroll
    for (int i = 0; i < 8; ++i)
        sP[warp * 256 + i * 32 + lane] = hsum2(accx[i]) + hsum2(accy[i]);
    __syncthreads();

    // thread t owns (gi = i0 + t>>5, j = j0 + t&31); fixed-order 8-warp sum
    float v = sP[tid];
    #pragma unroll
    for (int w = 1; w < 8; ++w) v += sP[w * 256 + tid];

    const int gi = i0 + (tid >> 5);
    const int j  = j0 + (tid & 31);
    gS[gi * N_VID + j] = v / ((float)nclips[gi] * (float)ncaps[j]);
}

// ===== K3: hinge loss + deterministic reduce ================================
// 64 blocks x 256 threads; block handles 4 rows of S. Diagonal gathered to
// smem once per block. Last block out does the final 64-partial reduce.
__global__ __launch_bounds__(256) void k_loss(float* __restrict__ out) {
    __shared__ float sdiag[N_VID];
    __shared__ float sred[256];
    __shared__ unsigned sLast;

    const int tid = threadIdx.x;
    const int bid = blockIdx.x;

    sdiag[tid] = gS[tid * (N_VID + 1)];   // S[t][t]
    __syncthreads();

    const int i  = bid * 4 + (tid >> 6);
    const int j4 = (tid & 63) * 4;
    const float4 sv = reinterpret_cast<const float4*>(gS)[i * (N_VID / 4) + (tid & 63)];
    const float di = sdiag[i];

    float contrib = 0.f;
    {
        const float v[4] = {sv.x, sv.y, sv.z, sv.w};
        #pragma unroll
        for (int q = 0; q < 4; ++q) {
            const int j = j4 + q;
            if (j != i)
                contrib += fmaxf(v[q] - di, 0.f) + fmaxf(v[q] - sdiag[j], 0.f);
        }
    }

    sred[tid] = contrib;
    __syncthreads();
    for (int o = 128; o > 0; o >>= 1) {
        if (tid < o) sred[tid] += sred[tid + o];
        __syncthreads();
    }
    if (tid == 0) gPart[bid] = sred[0];

    // last-block-out final reduce
    if (tid == 0) {
        __threadfence();
        sLast = (atomicAdd(&gDone, 1u) == 63u) ? 1u : 0u;
    }
    __syncthreads();
    if (sLast) {
        if (tid == 0) __threadfence();
        __syncthreads();
        sred[tid] = (tid < 64) ? gPart[tid] : 0.f;
        __syncthreads();
        for (int o = 128; o > 0; o >>= 1) {
            if (tid < o) sred[tid] += sred[tid + o];
            __syncthreads();
        }
        if (tid == 0) {
            out[0] = sred[0];
            gDone  = 0;    // replay-safe reset
        }
    }
}

extern "C" void kernel_launch(void* const* d_in, const int* in_sizes, int n_in,
                              void* d_out, int out_size) {
    const float* im     = (const float*)d_in[0];
    const float* s      = (const float*)d_in[1];
    const int*   nclips = (const int*)d_in[2];
    const int*   ncaps  = (const int*)d_in[3];
    float*       out    = (float*)d_out;

    k_segsum<<<512, 256>>>(im, s, nclips, ncaps);
    k_gemm  <<<256, 256>>>(nclips, ncaps);
    k_loss  <<<64, 256>>>(out);
}